// round 12
// baseline (speedup 1.0000x reference)
#include <cuda_runtime.h>
#include <cuda_fp16.h>
#include <math.h>
#include <math_constants.h>
#include <cstdint>

// ---------------- problem constants ----------------
#define BATCH      4
#define SEQ        512
#define HID        1024
#define HS         64
#define ENT_HEADS  2
#define REL_HEADS  24
#define TOT_HEADS  (ENT_HEADS + 2 * REL_HEADS)   // 50
#define N_ENT      (ENT_HEADS * 2 * HS)          // 256
#define N_REL      (REL_HEADS * 2 * HS)          // 3072
#define N_TOT      (N_ENT + 2 * N_REL)           // 6400
#define TOKENS     (BATCH * SEQ)                 // 2048
#define MAX_LEN    1024
#define BH         (BATCH * TOT_HEADS)           // 200

// work queue: 800 proj tiles (50 heads x 16 m-tiles of 128) then 3200 logits tiles
#define PROJ_ITEMS   (TOT_HEADS * (TOKENS / 128))            // 800
#define LOG_ITEMS    (TOT_HEADS * BATCH * 16)                // 3200
#define TOTAL_ITEMS  (PROJ_ITEMS + LOG_ITEMS)
#define PERSIST_CTAS 296
#define HEAD_TILES   (TOKENS / 128)                          // 16

// prep kernel grid partition
#define PREP_W_BLOCKS   ((N_TOT / 32) * (HID / 32))          // 6400
#define PREP_X_BLOCKS   (TOKENS * HID / 4 / 256)             // 2048
#define PREP_R_BLOCKS   (MAX_LEN * 16 / 256)                 // 64
#define PREP_B_BLOCKS   ((N_TOT + 255) / 256)                // 25
#define PREP_S_BLOCKS   1
#define PREP_GRID       (PREP_W_BLOCKS + PREP_X_BLOCKS + PREP_R_BLOCKS + PREP_B_BLOCKS + PREP_S_BLOCKS)

// ---------------- device scratch ----------------
__device__ __half g_x[TOKENS * HID];
__device__ __half g_wt[N_TOT * HID];      // transposed weights [n][k]
__device__ __half g_q[BH * SEQ * HS];
__device__ __half g_k[BH * SEQ * HS];
__device__ float g_bias[N_TOT];
__device__ float g_cos[MAX_LEN * 16];
__device__ float g_sin[MAX_LEN * 16];
__device__ unsigned g_work;
__device__ int g_head_done[TOT_HEADS];

// ---------------- ptx helpers (sm_80+ only: no tcgen05) ----------------
__device__ __forceinline__ uint32_t smem_u32(const void* p) {
    uint32_t a;
    asm("{ .reg .u64 t; cvta.to.shared.u64 t, %1; cvt.u32.u64 %0, t; }" : "=r"(a) : "l"(p));
    return a;
}
__device__ __forceinline__ void cp16(uint32_t saddr, const void* g) {
    asm volatile("cp.async.cg.shared.global [%0], [%1], 16;" :: "r"(saddr), "l"(g) : "memory");
}
#define CP_COMMIT() asm volatile("cp.async.commit_group;" ::: "memory")

__device__ __forceinline__ void ldsm_x4(uint32_t* r, uint32_t addr) {
    asm volatile("ldmatrix.sync.aligned.m8n8.x4.shared.b16 {%0,%1,%2,%3}, [%4];"
        : "=r"(r[0]), "=r"(r[1]), "=r"(r[2]), "=r"(r[3]) : "r"(addr));
}
// f16 inputs, f16 accumulators: C (2 regs = 4 halves) += A (4 regs) * B (2 regs)
__device__ __forceinline__ void mma16816h(uint32_t* c, const uint32_t* a, const uint32_t* b) {
    asm volatile(
        "mma.sync.aligned.m16n8k16.row.col.f16.f16.f16.f16 "
        "{%0,%1}, {%2,%3,%4,%5}, {%6,%7}, {%0,%1};"
        : "+r"(c[0]), "+r"(c[1])
        : "r"(a[0]), "r"(a[1]), "r"(a[2]), "r"(a[3]), "r"(b[0]), "r"(b[1]));
}

// ---------------- kernel 1: fused prep ----------------
__global__ __launch_bounds__(256)
void prep_kernel(const float* __restrict__ X,
                 const float* __restrict__ W_ent, const float* __restrict__ W_head,
                 const float* __restrict__ W_tail,
                 const float* __restrict__ b_ent, const float* __restrict__ b_head,
                 const float* __restrict__ b_tail) {
    __shared__ float t[32][33];
    int bid = blockIdx.x;
    int tid = threadIdx.x;

    if (bid < PREP_W_BLOCKS) {
        int nblk = bid / (HID / 32);
        int kblk = bid % (HID / 32);
        int gn0 = nblk * 32;
        int k0  = kblk * 32;
        const float* W; int N; int loc;
        if (gn0 < N_ENT)                { W = W_ent;  N = N_ENT; loc = gn0; }
        else if (gn0 < N_ENT + N_REL)   { W = W_head; N = N_REL; loc = gn0 - N_ENT; }
        else                            { W = W_tail; N = N_REL; loc = gn0 - N_ENT - N_REL; }
        int tx = tid & 31, ty = tid >> 5;
#pragma unroll
        for (int i = 0; i < 4; ++i)
            t[ty + i * 8][tx] = W[(size_t)(k0 + ty + i * 8) * N + loc + tx];
        __syncthreads();
#pragma unroll
        for (int i = 0; i < 4; ++i)
            g_wt[(size_t)(gn0 + ty + i * 8) * HID + k0 + tx] =
                __float2half(t[tx][ty + i * 8]);
        return;
    }
    bid -= PREP_W_BLOCKS;

    if (bid < PREP_X_BLOCKS) {
        int i = bid * 256 + tid;
        float4 v = ((const float4*)X)[i];
        ((__half2*)g_x)[i * 2]     = __floats2half2_rn(v.x, v.y);
        ((__half2*)g_x)[i * 2 + 1] = __floats2half2_rn(v.z, v.w);
        return;
    }
    bid -= PREP_X_BLOCKS;

    if (bid < PREP_R_BLOCKS) {
        int tt = bid * 256 + tid;
        int pos = tt >> 4;
        int a   = tt & 15;
        float div = expf((float)(2 * a) * (-logf(10000.0f) / 32.0f));
        float ang = (float)pos * div;
        g_cos[tt] = cosf(ang);
        g_sin[tt] = sinf(ang);
        return;
    }
    bid -= PREP_R_BLOCKS;

    if (bid < PREP_B_BLOCKS) {
        int i = bid * 256 + tid;
        if (i >= N_TOT) return;
        float v;
        if (i < N_ENT)               v = b_ent[i];
        else if (i < N_ENT + N_REL)  v = b_head[i - N_ENT];
        else                         v = b_tail[i - N_ENT - N_REL];
        g_bias[i] = v;
        return;
    }

    // -------- sync-state reset --------
    if (tid < TOT_HEADS) g_head_done[tid] = 0;
    if (tid == 64)       g_work = 0;
}

// ---------------- persistent fused GEMM kernel ----------------
// proj tile: 128 tokens x 128 cols (one head), 8 warps 4x2, warp 32x64, BK=64,
// 3-stage cp.async => 110592B smem => 2 CTAs/SM (regs capped to 128).
#define PJ_STRIDE 72
#define PJ_ABUF   18432
#define PJ_STAGE  36864
#define PJ_SMEM   110592
// logits tile: 128x128, K=64, single-shot load (reuses the same smem).
#define LG_STRIDE 72
#define LG_BUF    18432

extern __shared__ __align__(128) char dsm[];

__device__ __forceinline__ void proj_tile(int head, int m0,
                                          const int* __restrict__ xp,
                                          const int* __restrict__ yp) {
    uint32_t sb = smem_u32(dsm);
    int tid = threadIdx.x, wid = tid >> 5, lane = tid & 31;
    int warp_m = (wid & 3) * 32, warp_n = (wid >> 2) * 64;

    const __half* Xp = g_x  + (size_t)m0 * HID;
    const __half* Wp = g_wt + (size_t)head * 128 * HID;

    uint32_t acc[2][8][2];
#pragma unroll
    for (int i = 0; i < 2; ++i)
#pragma unroll
        for (int j = 0; j < 8; ++j) { acc[i][j][0] = 0u; acc[i][j][1] = 0u; }

    int a_row = (lane & 7) + ((lane >> 3) & 1) * 8;
    int a_col = (lane >> 4) * 8;
    int b_row = (lane & 7) + ((lane >> 4) & 1) * 8;
    int b_col = ((lane >> 3) & 1) * 8;

#define PJ_ISSUE(stage, c) do {                                               \
    int k0 = (c) * 64;                                                        \
    uint32_t base = sb + (stage) * PJ_STAGE;                                  \
    _Pragma("unroll")                                                         \
    for (int it = 0; it < 4; ++it) {         /* A: 1024 16B units */          \
        int flat = it * 256 + tid;                                            \
        int rr = flat >> 3, jj = flat & 7;                                    \
        cp16(base + (uint32_t)(rr * 144 + jj * 16),                           \
             Xp + (size_t)rr * HID + k0 + jj * 8);                            \
    }                                                                         \
    _Pragma("unroll")                                                         \
    for (int it = 0; it < 4; ++it) {         /* B: 1024 16B units */          \
        int flat = it * 256 + tid;                                            \
        int rr = flat >> 3, jj = flat & 7;                                    \
        cp16(base + PJ_ABUF + (uint32_t)(rr * 144 + jj * 16),                 \
             Wp + (size_t)rr * HID + k0 + jj * 8);                            \
    }                                                                         \
    CP_COMMIT();                                                              \
} while (0)

    PJ_ISSUE(0, 0);
    PJ_ISSUE(1, 1);
    for (int c = 0; c < 16; ++c) {
        if (c < 15) asm volatile("cp.async.wait_group 1;" ::: "memory");
        else        asm volatile("cp.async.wait_group 0;" ::: "memory");
        __syncthreads();
        if (c + 2 < 16) PJ_ISSUE((c + 2) % 3, c + 2);

        uint32_t bA = sb + (c % 3) * PJ_STAGE;
#pragma unroll
        for (int k16 = 0; k16 < 64; k16 += 16) {
            uint32_t ah[2][4];
#pragma unroll
            for (int mi = 0; mi < 2; ++mi) {
                uint32_t ao = (uint32_t)((warp_m + mi * 16 + a_row) * PJ_STRIDE + a_col + k16) * 2;
                ldsm_x4(ah[mi], bA + ao);
            }
#pragma unroll
            for (int n2 = 0; n2 < 4; ++n2) {
                uint32_t bh[4];
                uint32_t bo = (uint32_t)((warp_n + n2 * 16 + b_row) * PJ_STRIDE + b_col + k16) * 2;
                ldsm_x4(bh, bA + PJ_ABUF + bo);
#pragma unroll
                for (int mi = 0; mi < 2; ++mi)
#pragma unroll
                    for (int t = 0; t < 2; ++t)
                        mma16816h(acc[mi][n2 * 2 + t], ah[mi], bh + 2 * t);
            }
        }
    }

    // epilogue: bias + 2D RoPE, write f16 q/k
    int qk = warp_n >> 6;
    __half* outp = qk ? g_k : g_q;
    int colbase = head * 128 + warp_n;
#pragma unroll
    for (int mi = 0; mi < 2; ++mi) {
#pragma unroll
        for (int h = 0; h < 2; ++h) {
            int row = m0 + warp_m + mi * 16 + (lane >> 2) + h * 8;
            int px = xp[row], py = yp[row];
            int b = row >> 9, s = row & 511;
            size_t obase = ((size_t)(b * TOT_HEADS + head) * SEQ + s) * HS;
#pragma unroll
            for (int ni = 0; ni < 8; ++ni) {
                int d = ni * 8 + 2 * (lane & 3);
                float2 cv = __half22float2(*(__half2*)&acc[mi][ni][h]);
                float v0 = cv.x + g_bias[colbase + d];
                float v1 = cv.y + g_bias[colbase + d + 1];
                int p = (d < 32) ? px : py;
                int a = (d & 31) >> 1;
                float cc = g_cos[p * 16 + a], sn = g_sin[p * 16 + a];
                float o0 = v0 * cc - v1 * sn;
                float o1 = v1 * cc + v0 * sn;
                *(__half2*)(outp + obase + d) = __floats2half2_rn(o0, o1);
            }
        }
    }
}

__device__ __forceinline__ void logits_tile(int bh, int m0, int n0,
                                            const int* __restrict__ mask,
                                            float* __restrict__ out) {
    uint32_t sb = smem_u32(dsm);
    int tid = threadIdx.x, wid = tid >> 5, lane = tid & 31;
    int b = bh / TOT_HEADS, g = bh % TOT_HEADS;
    int warp_m = (wid & 3) * 32, warp_n = (wid >> 2) * 64;

    const __half* Qb = g_q + (size_t)bh * SEQ * HS;
    const __half* Kb = g_k + (size_t)bh * SEQ * HS;

#pragma unroll
    for (int it = 0; it < 4; ++it) {
        int flat = it * 256 + tid;
        int r = flat >> 3, j = flat & 7;
        uint32_t so = (uint32_t)(r * LG_STRIDE + j * 8) * 2;
        cp16(sb + so,          Qb + (size_t)(m0 + r) * HS + j * 8);
        cp16(sb + LG_BUF + so, Kb + (size_t)(n0 + r) * HS + j * 8);
    }
    CP_COMMIT();
    asm volatile("cp.async.wait_group 0;" ::: "memory");
    __syncthreads();

    uint32_t acc[2][8][2];
#pragma unroll
    for (int i = 0; i < 2; ++i)
#pragma unroll
        for (int j = 0; j < 8; ++j) { acc[i][j][0] = 0u; acc[i][j][1] = 0u; }

    int a_row = (lane & 7) + ((lane >> 3) & 1) * 8;
    int a_col = (lane >> 4) * 8;
    int b_row = (lane & 7) + ((lane >> 4) & 1) * 8;
    int b_col = ((lane >> 3) & 1) * 8;

#pragma unroll
    for (int k16 = 0; k16 < 64; k16 += 16) {
        uint32_t ah[2][4];
#pragma unroll
        for (int mi = 0; mi < 2; ++mi) {
            uint32_t ao = (uint32_t)((warp_m + mi * 16 + a_row) * LG_STRIDE + a_col + k16) * 2;
            ldsm_x4(ah[mi], sb + ao);
        }
#pragma unroll
        for (int n2 = 0; n2 < 4; ++n2) {
            uint32_t bhf[4];
            uint32_t bo = (uint32_t)((warp_n + n2 * 16 + b_row) * LG_STRIDE + b_col + k16) * 2;
            ldsm_x4(bhf, sb + LG_BUF + bo);
#pragma unroll
            for (int mi = 0; mi < 2; ++mi)
#pragma unroll
                for (int t = 0; t < 2; ++t)
                    mma16816h(acc[mi][n2 * 2 + t], ah[mi], bhf + 2 * t);
        }
    }

    const int* mrow = mask + b * SEQ;
    bool is_ent = (g < ENT_HEADS);
#pragma unroll
    for (int mi = 0; mi < 2; ++mi) {
#pragma unroll
        for (int h = 0; h < 2; ++h) {
            int m = m0 + warp_m + mi * 16 + (lane >> 2) + h * 8;
            bool pm = (mrow[m] > 0);
            float* orow = out + ((size_t)bh * SEQ + m) * SEQ;
#pragma unroll
            for (int ni = 0; ni < 8; ++ni) {
                int n = n0 + warp_n + ni * 8 + 2 * (lane & 3);
                float2 cv = __half22float2(*(__half2*)&acc[mi][ni][h]);
                float v0 = cv.x;
                float v1 = cv.y;
                if (!(pm && mrow[n] > 0))     v0 = -CUDART_INF_F;
                if (!(pm && mrow[n + 1] > 0)) v1 = -CUDART_INF_F;
                if (is_ent) {
                    if (m > n)     v0 -= 1e12f;
                    if (m > n + 1) v1 -= 1e12f;
                }
                __stcs(reinterpret_cast<float2*>(orow + n),
                       make_float2(v0 * 0.125f, v1 * 0.125f));
            }
        }
    }
}

__global__ __launch_bounds__(256, 2)
void fused_mma_kernel(const int* __restrict__ xp, const int* __restrict__ yp,
                      const int* __restrict__ mask, float* __restrict__ out) {
    __shared__ int s_item;
    while (true) {
        __syncthreads();                       // also protects smem reuse across items
        if (threadIdx.x == 0) s_item = (int)atomicAdd(&g_work, 1u);
        __syncthreads();
        int item = s_item;
        if (item >= TOTAL_ITEMS) return;

        if (item < PROJ_ITEMS) {
            int head = item >> 4;              // 16 m-tiles per head, heads in order
            int m0   = (item & 15) * 128;
            proj_tile(head, m0, xp, yp);
            __syncthreads();
            if (threadIdx.x == 0) {
                __threadfence();
                atomicAdd(&g_head_done[head], 1);
            }
        } else {
            int l = item - PROJ_ITEMS;
            int g = l >> 6;                    // 64 tiles per head (4 batches x 16)
            int r = l & 63;
            int b = r >> 4;
            int t = r & 15;
            if (threadIdx.x == 0) {
                while (atomicAdd(&g_head_done[g], 0) < HEAD_TILES) __nanosleep(64);
            }
            __syncthreads();
            logits_tile(b * TOT_HEADS + g, (t >> 2) * 128, (t & 3) * 128, mask, out);
        }
    }
}

// ---------------- launch ----------------
extern "C" void kernel_launch(void* const* d_in, const int* in_sizes, int n_in,
                              void* d_out, int out_size) {
    const float* x      = (const float*)d_in[0];
    const int*   mask   = (const int*)  d_in[1];
    const int*   xp     = (const int*)  d_in[2];
    const int*   yp     = (const int*)  d_in[3];
    const float* W_ent  = (const float*)d_in[4];
    const float* b_ent  = (const float*)d_in[5];
    const float* W_head = (const float*)d_in[6];
    const float* b_head = (const float*)d_in[7];
    const float* W_tail = (const float*)d_in[8];
    const float* b_tail = (const float*)d_in[9];
    float* out = (float*)d_out;

    cudaFuncSetAttribute(fused_mma_kernel, cudaFuncAttributeMaxDynamicSharedMemorySize, PJ_SMEM);

    prep_kernel<<<PREP_GRID, 256>>>(x, W_ent, W_head, W_tail, b_ent, b_head, b_tail);

    fused_mma_kernel<<<PERSIST_CTAS, 256, PJ_SMEM>>>(xp, yp, mask, out);
}

// round 13
// speedup vs baseline: 1.1399x; 1.1399x over previous
#include <cuda_runtime.h>
#include <cuda_fp16.h>
#include <math.h>
#include <math_constants.h>
#include <cstdint>

// ---------------- problem constants ----------------
#define BATCH      4
#define SEQ        512
#define HID        1024
#define HS         64
#define ENT_HEADS  2
#define REL_HEADS  24
#define TOT_HEADS  (ENT_HEADS + 2 * REL_HEADS)   // 50
#define N_ENT      (ENT_HEADS * 2 * HS)          // 256
#define N_REL      (REL_HEADS * 2 * HS)          // 3072
#define N_TOT      (N_ENT + 2 * N_REL)           // 6400
#define TOKENS     (BATCH * SEQ)                 // 2048
#define MAX_LEN    1024
#define BH         (BATCH * TOT_HEADS)           // 200

// work queue: 400 proj tiles (50 heads x 8 m-tiles of 256) then 1600 logits tiles
#define HEAD_TILES   (TOKENS / 256)                          // 8
#define PROJ_ITEMS   (TOT_HEADS * HEAD_TILES)                // 400
#define LOG_ITEMS    (TOT_HEADS * BATCH * 8)                 // 1600 (2 m x 4 n per bh)
#define TOTAL_ITEMS  (PROJ_ITEMS + LOG_ITEMS)
#define PERSIST_CTAS 296

// prep kernel grid partition
#define PREP_W_BLOCKS   ((N_TOT / 32) * (HID / 32))          // 6400
#define PREP_X_BLOCKS   (TOKENS * HID / 4 / 256)             // 2048
#define PREP_R_BLOCKS   (MAX_LEN * 16 / 256)                 // 64
#define PREP_B_BLOCKS   ((N_TOT + 255) / 256)                // 25
#define PREP_S_BLOCKS   1
#define PREP_GRID       (PREP_W_BLOCKS + PREP_X_BLOCKS + PREP_R_BLOCKS + PREP_B_BLOCKS + PREP_S_BLOCKS)

// ---------------- device scratch ----------------
__device__ __half g_x[TOKENS * HID];
__device__ __half g_wt[N_TOT * HID];      // transposed weights [n][k]
__device__ __half g_q[BH * SEQ * HS];
__device__ __half g_k[BH * SEQ * HS];
__device__ float g_bias[N_TOT];
__device__ float g_cos[MAX_LEN * 16];
__device__ float g_sin[MAX_LEN * 16];
__device__ unsigned g_work;
__device__ int g_head_done[TOT_HEADS];

// ---------------- ptx helpers (sm_80+ only: no tcgen05) ----------------
__device__ __forceinline__ uint32_t smem_u32(const void* p) {
    uint32_t a;
    asm("{ .reg .u64 t; cvta.to.shared.u64 t, %1; cvt.u32.u64 %0, t; }" : "=r"(a) : "l"(p));
    return a;
}
__device__ __forceinline__ void cp16(uint32_t saddr, const void* g) {
    asm volatile("cp.async.cg.shared.global [%0], [%1], 16;" :: "r"(saddr), "l"(g) : "memory");
}
#define CP_COMMIT() asm volatile("cp.async.commit_group;" ::: "memory")

__device__ __forceinline__ void ldsm_x4(uint32_t* r, uint32_t addr) {
    asm volatile("ldmatrix.sync.aligned.m8n8.x4.shared.b16 {%0,%1,%2,%3}, [%4];"
        : "=r"(r[0]), "=r"(r[1]), "=r"(r[2]), "=r"(r[3]) : "r"(addr));
}
// f16 inputs, f16 accumulators: C (2 regs = 4 halves) += A (4 regs) * B (2 regs)
__device__ __forceinline__ void mma16816h(uint32_t* c, const uint32_t* a, const uint32_t* b) {
    asm volatile(
        "mma.sync.aligned.m16n8k16.row.col.f16.f16.f16.f16 "
        "{%0,%1}, {%2,%3,%4,%5}, {%6,%7}, {%0,%1};"
        : "+r"(c[0]), "+r"(c[1])
        : "r"(a[0]), "r"(a[1]), "r"(a[2]), "r"(a[3]), "r"(b[0]), "r"(b[1]));
}

// ---------------- kernel 1: fused prep ----------------
__global__ __launch_bounds__(256)
void prep_kernel(const float* __restrict__ X,
                 const float* __restrict__ W_ent, const float* __restrict__ W_head,
                 const float* __restrict__ W_tail,
                 const float* __restrict__ b_ent, const float* __restrict__ b_head,
                 const float* __restrict__ b_tail) {
    __shared__ float t[32][33];
    int bid = blockIdx.x;
    int tid = threadIdx.x;

    if (bid < PREP_W_BLOCKS) {
        int nblk = bid / (HID / 32);
        int kblk = bid % (HID / 32);
        int gn0 = nblk * 32;
        int k0  = kblk * 32;
        const float* W; int N; int loc;
        if (gn0 < N_ENT)                { W = W_ent;  N = N_ENT; loc = gn0; }
        else if (gn0 < N_ENT + N_REL)   { W = W_head; N = N_REL; loc = gn0 - N_ENT; }
        else                            { W = W_tail; N = N_REL; loc = gn0 - N_ENT - N_REL; }
        int tx = tid & 31, ty = tid >> 5;
#pragma unroll
        for (int i = 0; i < 4; ++i)
            t[ty + i * 8][tx] = W[(size_t)(k0 + ty + i * 8) * N + loc + tx];
        __syncthreads();
#pragma unroll
        for (int i = 0; i < 4; ++i)
            g_wt[(size_t)(gn0 + ty + i * 8) * HID + k0 + tx] =
                __float2half(t[tx][ty + i * 8]);
        return;
    }
    bid -= PREP_W_BLOCKS;

    if (bid < PREP_X_BLOCKS) {
        int i = bid * 256 + tid;
        float4 v = ((const float4*)X)[i];
        ((__half2*)g_x)[i * 2]     = __floats2half2_rn(v.x, v.y);
        ((__half2*)g_x)[i * 2 + 1] = __floats2half2_rn(v.z, v.w);
        return;
    }
    bid -= PREP_X_BLOCKS;

    if (bid < PREP_R_BLOCKS) {
        int tt = bid * 256 + tid;
        int pos = tt >> 4;
        int a   = tt & 15;
        float div = expf((float)(2 * a) * (-logf(10000.0f) / 32.0f));
        float ang = (float)pos * div;
        g_cos[tt] = cosf(ang);
        g_sin[tt] = sinf(ang);
        return;
    }
    bid -= PREP_R_BLOCKS;

    if (bid < PREP_B_BLOCKS) {
        int i = bid * 256 + tid;
        if (i >= N_TOT) return;
        float v;
        if (i < N_ENT)               v = b_ent[i];
        else if (i < N_ENT + N_REL)  v = b_head[i - N_ENT];
        else                         v = b_tail[i - N_ENT - N_REL];
        g_bias[i] = v;
        return;
    }

    // -------- sync-state reset --------
    if (tid < TOT_HEADS) g_head_done[tid] = 0;
    if (tid == 64)       g_work = 0;
}

// ---------------- persistent fused GEMM kernel ----------------
// proj tile: 256 tokens x 128 cols (one head), 8 warps 4x2, warp 64x64, BK=64,
// 2-stage cp.async. Stage: A 256x72 (36864B) + B 128x72 (18432B) = 55296; x2 = 110592.
#define PJ_STRIDE 72
#define PJ_ABUF   36864
#define PJ_STAGE  55296
#define PJ_SMEM   110592
// logits tile: 256x128, K=64, single-shot load. Q 256x72 (36864) | K 128x72 (18432).
#define LG_STRIDE 72
#define LG_KOFF   36864

extern __shared__ __align__(128) char dsm[];

__device__ __forceinline__ void proj_tile(int head, int m0,
                                          const int* __restrict__ xp,
                                          const int* __restrict__ yp) {
    uint32_t sb = smem_u32(dsm);
    int tid = threadIdx.x, wid = tid >> 5, lane = tid & 31;
    int warp_m = (wid & 3) * 64, warp_n = (wid >> 2) * 64;

    const __half* Xp = g_x  + (size_t)m0 * HID;
    const __half* Wp = g_wt + (size_t)head * 128 * HID;

    uint32_t acc[4][8][2];
#pragma unroll
    for (int i = 0; i < 4; ++i)
#pragma unroll
        for (int j = 0; j < 8; ++j) { acc[i][j][0] = 0u; acc[i][j][1] = 0u; }

    int a_row = (lane & 7) + ((lane >> 3) & 1) * 8;
    int a_col = (lane >> 4) * 8;
    int b_row = (lane & 7) + ((lane >> 4) & 1) * 8;
    int b_col = ((lane >> 3) & 1) * 8;

#define PJ_ISSUE(stage, c) do {                                               \
    int k0 = (c) * 64;                                                        \
    uint32_t base = sb + (stage) * PJ_STAGE;                                  \
    _Pragma("unroll")                                                         \
    for (int it = 0; it < 8; ++it) {         /* A: 2048 16B units */          \
        int flat = it * 256 + tid;                                            \
        int rr = flat >> 3, jj = flat & 7;                                    \
        cp16(base + (uint32_t)(rr * 144 + jj * 16),                           \
             Xp + (size_t)rr * HID + k0 + jj * 8);                            \
    }                                                                         \
    _Pragma("unroll")                                                         \
    for (int it = 0; it < 4; ++it) {         /* B: 1024 16B units */          \
        int flat = it * 256 + tid;                                            \
        int rr = flat >> 3, jj = flat & 7;                                    \
        cp16(base + PJ_ABUF + (uint32_t)(rr * 144 + jj * 16),                 \
             Wp + (size_t)rr * HID + k0 + jj * 8);                            \
    }                                                                         \
    CP_COMMIT();                                                              \
} while (0)

    PJ_ISSUE(0, 0);
    for (int c = 0; c < 16; ++c) {
        int st = c & 1;
        if (c + 1 < 16) {
            PJ_ISSUE(st ^ 1, c + 1);
            asm volatile("cp.async.wait_group 1;" ::: "memory");
        } else {
            asm volatile("cp.async.wait_group 0;" ::: "memory");
        }
        __syncthreads();

        uint32_t bA = sb + st * PJ_STAGE;
#pragma unroll
        for (int k16 = 0; k16 < 64; k16 += 16) {
            uint32_t ah[4][4];
#pragma unroll
            for (int mi = 0; mi < 4; ++mi) {
                uint32_t ao = (uint32_t)((warp_m + mi * 16 + a_row) * PJ_STRIDE + a_col + k16) * 2;
                ldsm_x4(ah[mi], bA + ao);
            }
#pragma unroll
            for (int n2 = 0; n2 < 4; ++n2) {
                uint32_t bh[4];
                uint32_t bo = (uint32_t)((warp_n + n2 * 16 + b_row) * PJ_STRIDE + b_col + k16) * 2;
                ldsm_x4(bh, bA + PJ_ABUF + bo);
#pragma unroll
                for (int mi = 0; mi < 4; ++mi)
#pragma unroll
                    for (int t = 0; t < 2; ++t)
                        mma16816h(acc[mi][n2 * 2 + t], ah[mi], bh + 2 * t);
            }
        }
        __syncthreads();
    }

    // epilogue: bias + 2D RoPE, write f16 q/k
    int qk = warp_n >> 6;
    __half* outp = qk ? g_k : g_q;
    int colbase = head * 128 + warp_n;
#pragma unroll
    for (int mi = 0; mi < 4; ++mi) {
#pragma unroll
        for (int h = 0; h < 2; ++h) {
            int row = m0 + warp_m + mi * 16 + (lane >> 2) + h * 8;
            int px = xp[row], py = yp[row];
            int b = row >> 9, s = row & 511;
            size_t obase = ((size_t)(b * TOT_HEADS + head) * SEQ + s) * HS;
#pragma unroll
            for (int ni = 0; ni < 8; ++ni) {
                int d = ni * 8 + 2 * (lane & 3);
                float2 cv = __half22float2(*(__half2*)&acc[mi][ni][h]);
                float v0 = cv.x + g_bias[colbase + d];
                float v1 = cv.y + g_bias[colbase + d + 1];
                int p = (d < 32) ? px : py;
                int a = (d & 31) >> 1;
                float cc = g_cos[p * 16 + a], sn = g_sin[p * 16 + a];
                float o0 = v0 * cc - v1 * sn;
                float o1 = v1 * cc + v0 * sn;
                *(__half2*)(outp + obase + d) = __floats2half2_rn(o0, o1);
            }
        }
    }
}

__device__ __forceinline__ void logits_tile(int bh, int m0, int n0,
                                            const int* __restrict__ mask,
                                            float* __restrict__ out) {
    uint32_t sb = smem_u32(dsm);
    int tid = threadIdx.x, wid = tid >> 5, lane = tid & 31;
    int b = bh / TOT_HEADS, g = bh % TOT_HEADS;
    int warp_m = (wid & 3) * 64, warp_n = (wid >> 2) * 64;

    const __half* Qb = g_q + (size_t)bh * SEQ * HS;
    const __half* Kb = g_k + (size_t)bh * SEQ * HS;

#pragma unroll
    for (int it = 0; it < 8; ++it) {          // Q: 2048 16B units (256 rows)
        int flat = it * 256 + tid;
        int r = flat >> 3, j = flat & 7;
        cp16(sb + (uint32_t)(r * 144 + j * 16),
             Qb + (size_t)(m0 + r) * HS + j * 8);
    }
#pragma unroll
    for (int it = 0; it < 4; ++it) {          // K: 1024 16B units (128 rows)
        int flat = it * 256 + tid;
        int r = flat >> 3, j = flat & 7;
        cp16(sb + LG_KOFF + (uint32_t)(r * 144 + j * 16),
             Kb + (size_t)(n0 + r) * HS + j * 8);
    }
    CP_COMMIT();
    asm volatile("cp.async.wait_group 0;" ::: "memory");
    __syncthreads();

    uint32_t acc[4][8][2];
#pragma unroll
    for (int i = 0; i < 4; ++i)
#pragma unroll
        for (int j = 0; j < 8; ++j) { acc[i][j][0] = 0u; acc[i][j][1] = 0u; }

    int a_row = (lane & 7) + ((lane >> 3) & 1) * 8;
    int a_col = (lane >> 4) * 8;
    int b_row = (lane & 7) + ((lane >> 4) & 1) * 8;
    int b_col = ((lane >> 3) & 1) * 8;

#pragma unroll
    for (int k16 = 0; k16 < 64; k16 += 16) {
        uint32_t ah[4][4];
#pragma unroll
        for (int mi = 0; mi < 4; ++mi) {
            uint32_t ao = (uint32_t)((warp_m + mi * 16 + a_row) * LG_STRIDE + a_col + k16) * 2;
            ldsm_x4(ah[mi], sb + ao);
        }
#pragma unroll
        for (int n2 = 0; n2 < 4; ++n2) {
            uint32_t bhf[4];
            uint32_t bo = (uint32_t)((warp_n + n2 * 16 + b_row) * LG_STRIDE + b_col + k16) * 2;
            ldsm_x4(bhf, sb + LG_KOFF + bo);
#pragma unroll
            for (int mi = 0; mi < 4; ++mi)
#pragma unroll
                for (int t = 0; t < 2; ++t)
                    mma16816h(acc[mi][n2 * 2 + t], ah[mi], bhf + 2 * t);
        }
    }
    __syncthreads();   // smem reuse safety before next queue item

    const int* mrow = mask + b * SEQ;
    bool is_ent = (g < ENT_HEADS);
#pragma unroll
    for (int mi = 0; mi < 4; ++mi) {
#pragma unroll
        for (int h = 0; h < 2; ++h) {
            int m = m0 + warp_m + mi * 16 + (lane >> 2) + h * 8;
            bool pm = (mrow[m] > 0);
            float* orow = out + ((size_t)bh * SEQ + m) * SEQ;
#pragma unroll
            for (int ni = 0; ni < 8; ++ni) {
                int n = n0 + warp_n + ni * 8 + 2 * (lane & 3);
                float2 cv = __half22float2(*(__half2*)&acc[mi][ni][h]);
                float v0 = cv.x;
                float v1 = cv.y;
                if (!(pm && mrow[n] > 0))     v0 = -CUDART_INF_F;
                if (!(pm && mrow[n + 1] > 0)) v1 = -CUDART_INF_F;
                if (is_ent) {
                    if (m > n)     v0 -= 1e12f;
                    if (m > n + 1) v1 -= 1e12f;
                }
                __stcs(reinterpret_cast<float2*>(orow + n),
                       make_float2(v0 * 0.125f, v1 * 0.125f));
            }
        }
    }
}

__global__ __launch_bounds__(256, 2)
void fused_mma_kernel(const int* __restrict__ xp, const int* __restrict__ yp,
                      const int* __restrict__ mask, float* __restrict__ out) {
    __shared__ int s_item;
    while (true) {
        __syncthreads();                       // also protects smem reuse across items
        if (threadIdx.x == 0) s_item = (int)atomicAdd(&g_work, 1u);
        __syncthreads();
        int item = s_item;
        if (item >= TOTAL_ITEMS) return;

        if (item < PROJ_ITEMS) {
            int head = item >> 3;              // 8 m-tiles per head, heads in order
            int m0   = (item & 7) * 256;
            proj_tile(head, m0, xp, yp);
            __syncthreads();
            if (threadIdx.x == 0) {
                __threadfence();
                atomicAdd(&g_head_done[head], 1);
            }
        } else {
            int l = item - PROJ_ITEMS;
            int g = l >> 5;                    // 32 tiles per head (4 b x 2 m x 4 n)
            int r = l & 31;
            int b = r >> 3;
            int t = r & 7;
            if (threadIdx.x == 0) {
                while (atomicAdd(&g_head_done[g], 0) < HEAD_TILES) __nanosleep(64);
            }
            __syncthreads();
            logits_tile(b * TOT_HEADS + g, (t >> 2) * 256, (t & 3) * 128, mask, out);
        }
    }
}

// ---------------- launch ----------------
extern "C" void kernel_launch(void* const* d_in, const int* in_sizes, int n_in,
                              void* d_out, int out_size) {
    const float* x      = (const float*)d_in[0];
    const int*   mask   = (const int*)  d_in[1];
    const int*   xp     = (const int*)  d_in[2];
    const int*   yp     = (const int*)  d_in[3];
    const float* W_ent  = (const float*)d_in[4];
    const float* b_ent  = (const float*)d_in[5];
    const float* W_head = (const float*)d_in[6];
    const float* b_head = (const float*)d_in[7];
    const float* W_tail = (const float*)d_in[8];
    const float* b_tail = (const float*)d_in[9];
    float* out = (float*)d_out;

    cudaFuncSetAttribute(fused_mma_kernel, cudaFuncAttributeMaxDynamicSharedMemorySize, PJ_SMEM);

    prep_kernel<<<PREP_GRID, 256>>>(x, W_ent, W_head, W_tail, b_ent, b_head, b_tail);

    fused_mma_kernel<<<PERSIST_CTAS, 256, PJ_SMEM>>>(xp, yp, mask, out);
}